// round 1
// baseline (speedup 1.0000x reference)
#include <cuda_runtime.h>

// YOLO decode, warp-per-box.
// Inputs (metadata order): small [104,104,3,85] f32, middle [208,208,3,85] f32,
//                          large [416,416,3,85] f32, pre_scale [6,3,2] f32.
// Output: [681408, 6] f32, rows zeroed where conf <= 0.5.

#define FULLMASK 0xffffffffu

constexpr int N_SMALL  = 104 * 104 * 3;   // 32448
constexpr int N_MIDDLE = 208 * 208 * 3;   // 129792
constexpr int N_LARGE  = 416 * 416 * 3;   // 519168
constexpr int N_TOTAL  = N_SMALL + N_MIDDLE + N_LARGE;  // 681408

// Order-preserving float -> uint key (no NaNs in random-normal inputs).
static __device__ __forceinline__ unsigned ordkey(float f) {
    unsigned u = __float_as_uint(f);
    return (u & 0x80000000u) ? ~u : (u | 0x80000000u);
}

template<int S, int DECT>
static __device__ __forceinline__ void decode_box(
    const float* __restrict__ p, int r,
    const float* __restrict__ pre_scale,
    float* __restrict__ outrow, int lane)
{
    const float* base = p + (size_t)r * 85;

    // Three coalesced 128B loads cover the 85-word record exactly.
    float v0 = __ldg(base + lane);                                   // offsets 0..31
    float v1 = __ldg(base + 32 + lane);                              // offsets 32..63
    float v2 = (lane < 21) ? __ldg(base + 64 + lane) : -3.4e38f;     // offsets 64..84

    // ---- argmax over class logits (record offsets 5..84) ----
    float bestv = (lane >= 5) ? v0 : -3.4e38f;
    int   besto = lane;
    if (v1 > bestv) { bestv = v1; besto = 32 + lane; }
    if (lane < 21 && v2 > bestv) { bestv = v2; besto = 64 + lane; }

    unsigned key  = ordkey(bestv);
    unsigned mkey = __reduce_max_sync(FULLMASK, key);
    // first-occurrence tie-break: smallest offset among maxima
    unsigned cand = (key == mkey) ? (unsigned)besto : 0x7fffffffu;
    int      omin = (int)__reduce_min_sync(FULLMASK, cand);
    int      cls  = omin - 5;

    // ---- broadcast record[0..4] ----
    float conf  = __shfl_sync(FULLMASK, v0, 0);
    float tnext = __shfl_sync(FULLMASK, v0, (lane + 1) & 31);  // lane k holds record[k+1]

    if (lane < 6) {
        constexpr float invS = 1.0f / (float)S;
        const int i = r / (3 * S);        // grid row (axis 0) -> x offset
        const int j = (r / 3) % S;        // grid col (axis 1) -> y offset
        const int a = r % 3;              // anchor index

        float outv;
        if (lane == 0) {          // x = (sigmoid(p1) + i) / S
            outv = (1.0f / (1.0f + __expf(-tnext)) + (float)i) * invS;
        } else if (lane == 1) {   // y = (sigmoid(p2) + j) / S
            outv = (1.0f / (1.0f + __expf(-tnext)) + (float)j) * invS;
        } else if (lane == 2) {   // w = exp(p3) * anchor_w / 416
            float aw = __ldg(pre_scale + ((DECT * 3 + a) * 2 + 0));
            outv = __expf(tnext) * aw * (1.0f / 416.0f);
        } else if (lane == 3) {   // h = exp(p4) * anchor_h / 416
            float ah = __ldg(pre_scale + ((DECT * 3 + a) * 2 + 1));
            outv = __expf(tnext) * ah * (1.0f / 416.0f);
        } else if (lane == 4) {   // class index as float
            outv = (float)cls;
        } else {                  // conf
            outv = conf;
        }
        float m = (conf > 0.5f) ? 1.0f : 0.0f;
        outrow[lane] = outv * m;
    }
}

__global__ __launch_bounds__(256) void HEAD_12111807775050_kernel(
    const float* __restrict__ small,
    const float* __restrict__ middle,
    const float* __restrict__ large,
    const float* __restrict__ pre_scale,
    float* __restrict__ out)
{
    int gtid = blockIdx.x * blockDim.x + threadIdx.x;
    int wid  = gtid >> 5;          // one warp per box; warp never straddles levels
    int lane = gtid & 31;
    if (wid >= N_TOTAL) return;

    float* outrow = out + (size_t)wid * 6;
    if (wid < N_SMALL) {
        decode_box<104, 3>(small, wid, pre_scale, outrow, lane);
    } else if (wid < N_SMALL + N_MIDDLE) {
        decode_box<208, 4>(middle, wid - N_SMALL, pre_scale, outrow, lane);
    } else {
        decode_box<416, 5>(large, wid - N_SMALL - N_MIDDLE, pre_scale, outrow, lane);
    }
}

extern "C" void kernel_launch(void* const* d_in, const int* in_sizes, int n_in,
                              void* d_out, int out_size)
{
    const float* small     = (const float*)d_in[0];
    const float* middle    = (const float*)d_in[1];
    const float* large     = (const float*)d_in[2];
    const float* pre_scale = (const float*)d_in[3];
    float* out = (float*)d_out;

    const int threads = 256;                       // 8 warps = 8 boxes / block
    const int total_threads = N_TOTAL * 32;
    const int blocks = (total_threads + threads - 1) / threads;  // 85176
    HEAD_12111807775050_kernel<<<blocks, threads>>>(small, middle, large, pre_scale, out);
}

// round 2
// speedup vs baseline: 2.0297x; 2.0297x over previous
#include <cuda_runtime.h>

// YOLO decode, thread-per-box with smem staging.
// Inputs: small [104,104,3,85] f32, middle [208,208,3,85] f32,
//         large [416,416,3,85] f32, pre_scale [6,3,2] f32.
// Output: [681408, 6] f32, rows zeroed where conf <= 0.5.
//
// Design: each block stages BPB contiguous 85-float box records into smem via
// coalesced float4 loads, then each thread decodes one box from smem.
// Box stride 85 is coprime with 32 -> conflict-free scalar LDS.
// Level sizes divide evenly by BPB (96 for small, 128 for mid/large): no tails.

constexpr int N_SMALL  = 104 * 104 * 3;   // 32448  = 96  * 338
constexpr int N_MIDDLE = 208 * 208 * 3;   // 129792 = 128 * 1014
constexpr int N_LARGE  = 416 * 416 * 3;   // 519168 = 128 * 4056

template<int S, int DECT, int BPB>
__global__ __launch_bounds__(BPB) void decode_kernel(
    const float* __restrict__ in,        // this level's [S,S,3,85]
    const float* __restrict__ pre_scale, // [6,3,2]
    float* __restrict__ out)             // this level's [S*S*3, 6]
{
    __shared__ float s[BPB * 85];

    const int tid = threadIdx.x;
    const int blockBase = blockIdx.x * BPB;   // first box of this block

    // ---- coalesced stage-in: BPB*85 floats as float4 (BPB*85 % 4 == 0) ----
    constexpr int NV4 = BPB * 85 / 4;
    const float4* __restrict__ g4 = (const float4*)(in + (size_t)blockBase * 85);
    float4* s4 = (float4*)s;
    #pragma unroll
    for (int i = tid; i < NV4; i += BPB) s4[i] = g4[i];
    __syncthreads();

    // ---- one thread = one box ----
    const float* b = s + tid * 85;

    const float conf = b[0];
    const float tx = b[1], ty = b[2], tw = b[3], th = b[4];

    // argmax over 80 class logits, first-occurrence tie-break (strict >)
    float best = b[5];
    int   bi   = 0;
    #pragma unroll
    for (int k = 1; k < 80; k++) {
        float v = b[5 + k];
        if (v > best) { best = v; bi = k; }
    }

    const int r = blockBase + tid;     // box index within level
    const int i = r / (3 * S);         // grid axis-0 -> x offset
    const int j = (r / 3) % S;         // grid axis-1 -> y offset
    const int a = r % 3;               // anchor index

    constexpr float invS = 1.0f / (float)S;
    const float x = (1.0f / (1.0f + __expf(-tx)) + (float)i) * invS;
    const float y = (1.0f / (1.0f + __expf(-ty)) + (float)j) * invS;

    const float aw = __ldg(pre_scale + ((DECT * 3 + a) * 2 + 0));
    const float ah = __ldg(pre_scale + ((DECT * 3 + a) * 2 + 1));
    const float w = __expf(tw) * aw * (1.0f / 416.0f);
    const float h = __expf(th) * ah * (1.0f / 416.0f);

    const float m = (conf > 0.5f) ? 1.0f : 0.0f;

    float* o = out + (size_t)r * 6;
    o[0] = x * m;
    o[1] = y * m;
    o[2] = w * m;
    o[3] = h * m;
    o[4] = (float)bi * m;
    o[5] = conf * m;
}

extern "C" void kernel_launch(void* const* d_in, const int* in_sizes, int n_in,
                              void* d_out, int out_size)
{
    const float* small     = (const float*)d_in[0];
    const float* middle    = (const float*)d_in[1];
    const float* large     = (const float*)d_in[2];
    const float* pre_scale = (const float*)d_in[3];
    float* out = (float*)d_out;

    decode_kernel<104, 3,  96><<<N_SMALL  /  96,  96>>>(small,  pre_scale, out);
    decode_kernel<208, 4, 128><<<N_MIDDLE / 128, 128>>>(middle, pre_scale, out + (size_t)N_SMALL * 6);
    decode_kernel<416, 5, 128><<<N_LARGE  / 128, 128>>>(large,  pre_scale, out + (size_t)(N_SMALL + N_MIDDLE) * 6);
}

// round 3
// speedup vs baseline: 2.4225x; 1.1935x over previous
#include <cuda_runtime.h>

// YOLO decode, single launch, warp-autonomous staging, thread-per-box.
// Inputs: small [104,104,3,85] f32, middle [208,208,3,85] f32,
//         large [416,416,3,85] f32, pre_scale [6,3,2] f32.
// Output: [681408, 6] f32, rows zeroed where conf <= 0.5.
//
// Each global warp owns 32 consecutive boxes of the concatenated box space.
// Level boundaries (32448, 162240) are multiples of 32 -> warp never straddles.
// Warp stages its 32 records (680 float4, fully coalesced) into a private smem
// slice, __syncwarp only, then each lane decodes one box (stride-85 smem reads
// are bank-conflict-free since gcd(85,32)=1).

constexpr int N_SMALL  = 104 * 104 * 3;   // 32448
constexpr int N_MIDDLE = 208 * 208 * 3;   // 129792
constexpr int N_LARGE  = 416 * 416 * 3;   // 519168
constexpr int N_TOTAL  = N_SMALL + N_MIDDLE + N_LARGE;  // 681408
constexpr int N_WARPS  = N_TOTAL / 32;    // 21294
constexpr int WPB      = 4;               // warps per block (128 thr, 43.5KB smem)
constexpr int NBLK     = (N_WARPS + WPB - 1) / WPB;     // 5324

template<int S, int DECT>
static __device__ __forceinline__ void boxxform(
    int r, float tx, float ty, float tw, float th,
    const float* __restrict__ ps,
    float& x, float& y, float& w, float& h)
{
    const int i = r / (3 * S);   // grid axis-0 -> x offset (constant divide)
    const int j = (r / 3) % S;   // grid axis-1 -> y offset
    const int a = r % 3;         // anchor
    constexpr float invS = 1.0f / (float)S;
    x = (1.0f / (1.0f + __expf(-tx)) + (float)i) * invS;
    y = (1.0f / (1.0f + __expf(-ty)) + (float)j) * invS;
    const float aw = __ldg(ps + ((DECT * 3 + a) * 2 + 0));
    const float ah = __ldg(ps + ((DECT * 3 + a) * 2 + 1));
    w = __expf(tw) * aw * (1.0f / 416.0f);
    h = __expf(th) * ah * (1.0f / 416.0f);
}

__global__ __launch_bounds__(32 * WPB, 5) void HEAD_kernel(
    const float* __restrict__ small,
    const float* __restrict__ middle,
    const float* __restrict__ large,
    const float* __restrict__ pre_scale,
    float* __restrict__ out)
{
    __shared__ float sm[WPB][32 * 85];

    const int lane = threadIdx.x & 31;
    const int wIn  = threadIdx.x >> 5;
    const int gw   = blockIdx.x * WPB + wIn;     // global warp id
    if (gw >= N_WARPS) return;                   // warp-uniform exit

    const int boxBase = gw * 32;                 // global box index of lane 0

    // ---- warp-uniform level selection ----
    const float* in;
    int lvl, lvlStart;
    if (boxBase < N_SMALL)            { in = small;  lvl = 0; lvlStart = 0; }
    else if (boxBase < N_SMALL + N_MIDDLE) { in = middle; lvl = 1; lvlStart = N_SMALL; }
    else                              { in = large;  lvl = 2; lvlStart = N_SMALL + N_MIDDLE; }
    const int r0 = boxBase - lvlStart;           // level-local base box

    // ---- stage 32 records = 680 float4, coalesced, warp-private ----
    const float4* __restrict__ g4 = (const float4*)(in + (size_t)r0 * 85);
    float4* s4 = (float4*)sm[wIn];
    #pragma unroll
    for (int it = 0; it < 22; it++) {
        const int idx = lane + 32 * it;
        if (idx < 680) s4[idx] = g4[idx];
    }
    __syncwarp();

    // ---- decode one box per lane from smem ----
    const float* b = sm[wIn] + lane * 85;
    const float conf = b[0];
    const float tx = b[1], ty = b[2], tw = b[3], th = b[4];

    // argmax over 80 logits, two chains, first-occurrence tie-break
    float b0 = b[5];  int i0 = 0;
    float b1 = b[6];  int i1 = 1;
    #pragma unroll
    for (int k = 2; k < 80; k += 2) {
        const float v0 = b[5 + k];
        const float v1 = b[6 + k];
        if (v0 > b0) { b0 = v0; i0 = k; }
        if (v1 > b1) { b1 = v1; i1 = k + 1; }
    }
    const int bi = (b1 > b0 || (b1 == b0 && i1 < i0)) ? i1 : i0;

    const int r = r0 + lane;                     // level-local box index
    float x, y, w, h;
    if (lvl == 0)      boxxform<104, 3>(r, tx, ty, tw, th, pre_scale, x, y, w, h);
    else if (lvl == 1) boxxform<208, 4>(r, tx, ty, tw, th, pre_scale, x, y, w, h);
    else               boxxform<416, 5>(r, tx, ty, tw, th, pre_scale, x, y, w, h);

    const float m = (conf > 0.5f) ? 1.0f : 0.0f;
    float* o = out + (size_t)(boxBase + lane) * 6;
    o[0] = x * m;
    o[1] = y * m;
    o[2] = w * m;
    o[3] = h * m;
    o[4] = (float)bi * m;
    o[5] = conf * m;
}

extern "C" void kernel_launch(void* const* d_in, const int* in_sizes, int n_in,
                              void* d_out, int out_size)
{
    const float* small     = (const float*)d_in[0];
    const float* middle    = (const float*)d_in[1];
    const float* large     = (const float*)d_in[2];
    const float* pre_scale = (const float*)d_in[3];
    float* out = (float*)d_out;

    HEAD_kernel<<<NBLK, 32 * WPB>>>(small, middle, large, pre_scale, out);
}

// round 4
// speedup vs baseline: 2.8387x; 1.1718x over previous
#include <cuda_runtime.h>
#include <cstdint>

// YOLO decode: persistent warps, cp.async double-buffered staging, thread-per-box.
// Inputs: small [104,104,3,85] f32, middle [208,208,3,85] f32,
//         large [416,416,3,85] f32, pre_scale [6,3,2] f32.
// Output: [681408, 6] f32, rows zeroed where conf <= 0.5.

constexpr int N_SMALL  = 104 * 104 * 3;   // 32448
constexpr int N_MIDDLE = 208 * 208 * 3;   // 129792
constexpr int N_LARGE  = 416 * 416 * 3;   // 519168
constexpr int N_TOTAL  = N_SMALL + N_MIDDLE + N_LARGE;  // 681408
constexpr int N_TILES  = N_TOTAL / 32;    // 21294 tiles of 32 boxes
constexpr int WPB      = 2;               // 64 threads/block, 43.5KB smem/block
constexpr int NBLK     = 148 * 5;         // 740 blocks -> 5 resident/SM
constexpr int TOTW     = NBLK * WPB;      // 1480 persistent warps
constexpr int V4_PER_TILE = 32 * 85 / 4;  // 680 float4 per tile

static __device__ __forceinline__ void cp16(uint32_t dst_smem, const float4* src) {
    asm volatile("cp.async.cg.shared.global [%0], [%1], 16;\n"
                 :: "r"(dst_smem), "l"(src));
}
static __device__ __forceinline__ void cp_commit() {
    asm volatile("cp.async.commit_group;\n" ::: "memory");
}
template<int N>
static __device__ __forceinline__ void cp_wait() {
    asm volatile("cp.async.wait_group %0;\n" :: "n"(N) : "memory");
}

// tile -> (level base ptr, level id, level-local base box)
static __device__ __forceinline__ void tile_level(
    int t, const float* small, const float* middle, const float* large,
    const float*& in, int& lvl, int& r0)
{
    const int boxBase = t * 32;
    if (boxBase < N_SMALL)                 { in = small;  lvl = 0; r0 = boxBase; }
    else if (boxBase < N_SMALL + N_MIDDLE) { in = middle; lvl = 1; r0 = boxBase - N_SMALL; }
    else                                   { in = large;  lvl = 2; r0 = boxBase - N_SMALL - N_MIDDLE; }
}

template<int S, int DECT>
static __device__ __forceinline__ void boxxform(
    int r, float tx, float ty, float tw, float th,
    const float* __restrict__ ps,
    float& x, float& y, float& w, float& h)
{
    const int i = r / (3 * S);
    const int j = (r / 3) % S;
    const int a = r % 3;
    constexpr float invS = 1.0f / (float)S;
    x = (1.0f / (1.0f + __expf(-tx)) + (float)i) * invS;
    y = (1.0f / (1.0f + __expf(-ty)) + (float)j) * invS;
    const float aw = __ldg(ps + ((DECT * 3 + a) * 2 + 0));
    const float ah = __ldg(ps + ((DECT * 3 + a) * 2 + 1));
    w = __expf(tw) * aw * (1.0f / 416.0f);
    h = __expf(th) * ah * (1.0f / 416.0f);
}

__global__ __launch_bounds__(32 * WPB) void HEAD_kernel(
    const float* __restrict__ small,
    const float* __restrict__ middle,
    const float* __restrict__ large,
    const float* __restrict__ pre_scale,
    float* __restrict__ out)
{
    __shared__ float4 sm[WPB][2][V4_PER_TILE];

    const int lane = threadIdx.x & 31;
    const int wIn  = threadIdx.x >> 5;
    const int gw   = blockIdx.x * WPB + wIn;

    const uint32_t sbase[2] = {
        (uint32_t)__cvta_generic_to_shared(&sm[wIn][0][0]),
        (uint32_t)__cvta_generic_to_shared(&sm[wIn][1][0])
    };

    // ---- issue copies for one tile into buffer `buf` ----
    auto stage = [&](int t, int buf) {
        const float* in; int lvl, r0;
        tile_level(t, small, middle, large, in, lvl, r0);
        const float4* g4 = (const float4*)(in + (size_t)r0 * 85);
        const uint32_t sb = sbase[buf];
        #pragma unroll
        for (int j = 0; j < 22; j++) {
            const int idx = lane + 32 * j;
            if (idx < V4_PER_TILE) cp16(sb + idx * 16, g4 + idx);
        }
        cp_commit();
    };

    // ---- decode one tile from buffer `buf` ----
    auto compute = [&](int t, int buf) {
        const float* in_unused; int lvl, r0;
        tile_level(t, small, middle, large, in_unused, lvl, r0);

        const float* b = (const float*)&sm[wIn][buf][0] + lane * 85;
        const float conf = b[0];
        const float tx = b[1], ty = b[2], tw = b[3], th = b[4];

        float b0 = b[5];  int i0 = 0;
        float b1 = b[6];  int i1 = 1;
        #pragma unroll
        for (int k = 2; k < 80; k += 2) {
            const float v0 = b[5 + k];
            const float v1 = b[6 + k];
            if (v0 > b0) { b0 = v0; i0 = k; }
            if (v1 > b1) { b1 = v1; i1 = k + 1; }
        }
        const int bi = (b1 > b0 || (b1 == b0 && i1 < i0)) ? i1 : i0;

        const int r = r0 + lane;
        float x, y, w, h;
        if (lvl == 0)      boxxform<104, 3>(r, tx, ty, tw, th, pre_scale, x, y, w, h);
        else if (lvl == 1) boxxform<208, 4>(r, tx, ty, tw, th, pre_scale, x, y, w, h);
        else               boxxform<416, 5>(r, tx, ty, tw, th, pre_scale, x, y, w, h);

        const float m = (conf > 0.5f) ? 1.0f : 0.0f;
        float* o = out + (size_t)(t * 32 + lane) * 6;
        o[0] = x * m;
        o[1] = y * m;
        o[2] = w * m;
        o[3] = h * m;
        o[4] = (float)bi * m;
        o[5] = conf * m;
    };

    int t = gw;
    if (t >= N_TILES) return;     // never taken with TOTW < N_TILES; safety
    stage(t, 0);
    int cur = 0;

    while (true) {
        const int tn = t + TOTW;
        const bool have_next = (tn < N_TILES);
        if (have_next) {
            stage(tn, cur ^ 1);   // keep next tile's copies in flight
            cp_wait<1>();         // current tile's group complete
        } else {
            cp_wait<0>();
        }
        __syncwarp();
        compute(t, cur);
        __syncwarp();             // all lanes done reading before buffer reuse
        if (!have_next) break;
        t = tn;
        cur ^= 1;
    }
}

extern "C" void kernel_launch(void* const* d_in, const int* in_sizes, int n_in,
                              void* d_out, int out_size)
{
    const float* small     = (const float*)d_in[0];
    const float* middle    = (const float*)d_in[1];
    const float* large     = (const float*)d_in[2];
    const float* pre_scale = (const float*)d_in[3];
    float* out = (float*)d_out;

    HEAD_kernel<<<NBLK, 32 * WPB>>>(small, middle, large, pre_scale, out);
}